// round 1
// baseline (speedup 1.0000x reference)
#include <cuda_runtime.h>

// Problem constants
#define B_   64
#define C_   256
#define HW_  4096
#define EMB_ 512

// Scratch for the per-batch additive vector av[b][c] (allocation-free rule:
// __device__ global array).
__device__ float g_av[B_ * C_];

// ---------------------------------------------------------------------------
// Kernel A: av[b] = out_w @ (wv @ (kv_w[C:2C] @ cond_emb[b] + kv_b[C:]) + bv) + out_b
// One block per batch. Three warp-reduce dot stages through shared memory.
// Total work ~34 MFLOP; weights are L2-resident after the first wave.
// ---------------------------------------------------------------------------
__global__ void __launch_bounds__(256) compute_av_kernel(
    const float* __restrict__ cond_emb,   // (B, EMB)
    const float* __restrict__ in_proj_w,  // (3C, C) — wv = rows [2C, 3C)
    const float* __restrict__ in_proj_b,  // (3C,)
    const float* __restrict__ out_w,      // (C, C)
    const float* __restrict__ out_b,      // (C,)
    const float* __restrict__ kv_w,       // (2C, EMB) — v part = rows [C, 2C)
    const float* __restrict__ kv_b)       // (2C,)
{
    __shared__ float s_ce[EMB_];
    __shared__ float s_t1[C_];
    __shared__ float s_t2[C_];

    const int b    = blockIdx.x;
    const int tid  = threadIdx.x;
    const int lane = tid & 31;
    const int warp = tid >> 5;   // 8 warps

    // Load cond_emb[b]
    for (int i = tid; i < EMB_; i += 256)
        s_ce[i] = cond_emb[(size_t)b * EMB_ + i];
    __syncthreads();

    // Stage 1: v_in[j] = kv_w[C+j,:] . ce + kv_b[C+j]      (512-dot)
    for (int j = warp; j < C_; j += 8) {
        const float* row = kv_w + (size_t)(C_ + j) * EMB_;
        float acc = 0.f;
        #pragma unroll 4
        for (int k = lane; k < EMB_; k += 32)
            acc += row[k] * s_ce[k];
        #pragma unroll
        for (int o = 16; o > 0; o >>= 1)
            acc += __shfl_down_sync(0xffffffffu, acc, o);
        if (lane == 0) s_t1[j] = acc + kv_b[C_ + j];
    }
    __syncthreads();

    // Stage 2: v[i] = wv[i,:] . v_in + bv[i]               (256-dot)
    for (int i = warp; i < C_; i += 8) {
        const float* row = in_proj_w + (size_t)(2 * C_ + i) * C_;
        float acc = 0.f;
        #pragma unroll 4
        for (int k = lane; k < C_; k += 32)
            acc += row[k] * s_t1[k];
        #pragma unroll
        for (int o = 16; o > 0; o >>= 1)
            acc += __shfl_down_sync(0xffffffffu, acc, o);
        if (lane == 0) s_t2[i] = acc + in_proj_b[2 * C_ + i];
    }
    __syncthreads();

    // Stage 3: av[c] = out_w[c,:] . v + out_b[c]           (256-dot)
    for (int c = warp; c < C_; c += 8) {
        const float* row = out_w + (size_t)c * C_;
        float acc = 0.f;
        #pragma unroll 4
        for (int k = lane; k < C_; k += 32)
            acc += row[k] * s_t2[k];
        #pragma unroll
        for (int o = 16; o > 0; o >>= 1)
            acc += __shfl_down_sync(0xffffffffu, acc, o);
        if (lane == 0) g_av[b * C_ + c] = acc + out_b[c];
    }
}

// ---------------------------------------------------------------------------
// Kernel B: y[b,c,h,w] = x[b,c,h,w] + av[b,c]
// One block per (b,c) pair = 4096 contiguous floats = 1024 float4s.
// 256 threads x 4 float4 each. Pure streaming HBM kernel.
// ---------------------------------------------------------------------------
__global__ void __launch_bounds__(256) broadcast_add_kernel(
    const float* __restrict__ x,
    float* __restrict__ y)
{
    const int bc = blockIdx.x;                 // 0 .. B*C-1
    const float a = g_av[bc];

    const float4* __restrict__ xi = reinterpret_cast<const float4*>(x) + (size_t)bc * (HW_ / 4);
    float4* __restrict__       yo = reinterpret_cast<float4*>(y)       + (size_t)bc * (HW_ / 4);

    #pragma unroll
    for (int t = 0; t < 4; t++) {
        const int i = threadIdx.x + t * 256;
        float4 v = xi[i];
        v.x += a; v.y += a; v.z += a; v.w += a;
        yo[i] = v;
    }
}

extern "C" void kernel_launch(void* const* d_in, const int* in_sizes, int n_in,
                              void* d_out, int out_size)
{
    // metadata order: x, cond_emb, ln_gamma, ln_beta, in_proj_w, in_proj_b,
    //                 out_w, out_b, kv_w, kv_b
    const float* x         = (const float*)d_in[0];
    const float* cond_emb  = (const float*)d_in[1];
    // ln_gamma (d_in[2]) / ln_beta (d_in[3]) provably do not affect the output:
    // softmax over the size-1 KV axis is exactly 1, so q (and thus x_ln) cancels.
    const float* in_proj_w = (const float*)d_in[4];
    const float* in_proj_b = (const float*)d_in[5];
    const float* out_w     = (const float*)d_in[6];
    const float* out_b     = (const float*)d_in[7];
    const float* kv_w      = (const float*)d_in[8];
    const float* kv_b      = (const float*)d_in[9];
    float* y = (float*)d_out;

    compute_av_kernel<<<B_, 256>>>(cond_emb, in_proj_w, in_proj_b,
                                   out_w, out_b, kv_w, kv_b);
    broadcast_add_kernel<<<B_ * C_, 256>>>(x, y);
}

// round 2
// speedup vs baseline: 2.1322x; 2.1322x over previous
#include <cuda_runtime.h>

// Problem constants
#define B_   64
#define C_   256
#define HW_  4096
#define EMB_ 512

// Scratch (allocation-free rule: __device__ globals)
__device__ float g_t1[B_ * C_];   // v_in
__device__ float g_t2[B_ * C_];   // v
__device__ float g_av[B_ * C_];   // final additive vector

// ---------------------------------------------------------------------------
// Generic stage: out[b*C + r] = dot(W[r], in[b], LEN) + bias[r]
// One warp per (b, r). float4 vectorized loads. LEN is 512 or 256.
// Grid: B*C/8 blocks x 256 threads (8 warps).
// ---------------------------------------------------------------------------
template <int LEN>
__global__ void __launch_bounds__(256) stage_kernel(
    const float* __restrict__ W,      // (C_, LEN) row-major (pre-offset by caller)
    const float* __restrict__ invec,  // (B_, LEN)
    const float* __restrict__ bias,   // (C_,) pre-offset
    float* __restrict__ out)          // (B_, C_)
{
    const int warp = threadIdx.x >> 5;
    const int lane = threadIdx.x & 31;
    const int w    = blockIdx.x * 8 + warp;   // 0 .. B_*C_-1
    const int b    = w >> 8;                  // / C_
    const int r    = w & 255;                 // % C_

    const float4* __restrict__ wrow = reinterpret_cast<const float4*>(W + (size_t)r * LEN);
    const float4* __restrict__ xin  = reinterpret_cast<const float4*>(invec + (size_t)b * LEN);

    float acc = 0.f;
    #pragma unroll
    for (int k = lane; k < LEN / 4; k += 32) {
        float4 a = wrow[k];
        float4 c = xin[k];
        acc += a.x * c.x + a.y * c.y + a.z * c.z + a.w * c.w;
    }
    #pragma unroll
    for (int o = 16; o > 0; o >>= 1)
        acc += __shfl_down_sync(0xffffffffu, acc, o);
    if (lane == 0) out[w] = acc + bias[r];
}

// ---------------------------------------------------------------------------
// Kernel B: y[b,c,h,w] = x[b,c,h,w] + av[b,c]
// One block per (b,c) = 4096 contiguous floats = 1024 float4s.
// Streaming hints: zero reuse on x and y.
// ---------------------------------------------------------------------------
__global__ void __launch_bounds__(256) broadcast_add_kernel(
    const float* __restrict__ x,
    float* __restrict__ y)
{
    const int bc = blockIdx.x;                 // 0 .. B*C-1
    const float a = g_av[bc];

    const float4* __restrict__ xi = reinterpret_cast<const float4*>(x) + (size_t)bc * (HW_ / 4);
    float4* __restrict__       yo = reinterpret_cast<float4*>(y)       + (size_t)bc * (HW_ / 4);

    #pragma unroll
    for (int t = 0; t < 4; t++) {
        const int i = threadIdx.x + t * 256;
        float4 v = __ldcs(&xi[i]);
        v.x += a; v.y += a; v.z += a; v.w += a;
        __stcs(&yo[i], v);
    }
}

extern "C" void kernel_launch(void* const* d_in, const int* in_sizes, int n_in,
                              void* d_out, int out_size)
{
    // metadata order: x, cond_emb, ln_gamma, ln_beta, in_proj_w, in_proj_b,
    //                 out_w, out_b, kv_w, kv_b
    const float* x         = (const float*)d_in[0];
    const float* cond_emb  = (const float*)d_in[1];
    // ln_gamma/ln_beta provably do not affect the output: softmax over the
    // size-1 KV axis is exactly 1, so q (and thus x_ln) cancels.
    const float* in_proj_w = (const float*)d_in[4];
    const float* in_proj_b = (const float*)d_in[5];
    const float* out_w     = (const float*)d_in[6];
    const float* out_b     = (const float*)d_in[7];
    const float* kv_w      = (const float*)d_in[8];
    const float* kv_b      = (const float*)d_in[9];
    float* y = (float*)d_out;

    float *t1, *t2, *av;
    cudaGetSymbolAddress((void**)&t1, g_t1);
    cudaGetSymbolAddress((void**)&t2, g_t2);
    cudaGetSymbolAddress((void**)&av, g_av);

    const int grid = B_ * C_ / 8;   // 2048 blocks, one warp per output element

    // Stage 1: t1[b] = kv_w[C:2C] @ ce[b] + kv_b[C:]
    stage_kernel<EMB_><<<grid, 256>>>(kv_w + (size_t)C_ * EMB_, cond_emb,
                                      kv_b + C_, t1);
    // Stage 2: t2[b] = wv @ t1[b] + bv      (wv = in_proj_w rows [2C,3C))
    stage_kernel<C_><<<grid, 256>>>(in_proj_w + (size_t)2 * C_ * C_, t1,
                                    in_proj_b + 2 * C_, t2);
    // Stage 3: av[b] = out_w @ t2[b] + out_b
    stage_kernel<C_><<<grid, 256>>>(out_w, t2, out_b, av);

    // y = x + av broadcast
    broadcast_add_kernel<<<B_ * C_, 256>>>(x, y);
}